// round 1
// baseline (speedup 1.0000x reference)
#include <cuda_runtime.h>
#include <cuda_bf16.h>
#include <stdint.h>

#define NCN 100000
#define NRN 100000
#define HD  64

// ---------------- scratch (device globals: allocation-free) ----------------
__device__ float g_t_c[(size_t)NCN * HD]; // transformed src (customer side) / u_c
__device__ float g_t_r[(size_t)NRN * HD]; // transformed src (recipe side)   / u_r
__device__ float g_s_r[(size_t)NRN * HD]; // self term for recipes
__device__ float g_s_c[(size_t)NCN * HD]; // self term for customers
__device__ float g_a_r[(size_t)NRN * HD]; // aggregation accum (recipes)
__device__ float g_a_c[(size_t)NCN * HD]; // aggregation accum (customers)
__device__ float g_h_r[(size_t)NRN * HD]; // h_r then z_r
__device__ float g_h_c[(size_t)NCN * HD]; // h_c then z_c
__device__ int   g_dg_r[NRN];
__device__ int   g_dg_c[NCN];

// ---------------- kernels ----------------

__global__ void zero_k(float4* __restrict__ p, int n4) {
    int i = blockIdx.x * blockDim.x + threadIdx.x;
    if (i < n4) p[i] = make_float4(0.f, 0.f, 0.f, 0.f);
}

// Y[n,64] = X[n,K] @ W[K,64].  W cached in shared; one thread per row.
// All lanes read the same W address per step -> smem broadcast, FMA-bound.
__global__ void gemm_nk(const float* __restrict__ X, const float* __restrict__ W,
                        float* __restrict__ Y, int n, int K) {
    extern __shared__ float Ws[]; // K*64
    for (int i = threadIdx.x; i < K * HD; i += blockDim.x) Ws[i] = W[i];
    __syncthreads();
    int row = blockIdx.x * blockDim.x + threadIdx.x;
    if (row >= n) return;
    float acc[HD];
#pragma unroll
    for (int j = 0; j < HD; j++) acc[j] = 0.f;
    const float* xr = X + (size_t)row * K;
    for (int k = 0; k < K; k += 4) {
        float4 xv = *reinterpret_cast<const float4*>(xr + k);
        float xs[4] = {xv.x, xv.y, xv.z, xv.w};
#pragma unroll
        for (int kk = 0; kk < 4; kk++) {
            const float4* wrow = reinterpret_cast<const float4*>(Ws + (k + kk) * HD);
            float x = xs[kk];
#pragma unroll
            for (int j4 = 0; j4 < HD / 4; j4++) {
                float4 w = wrow[j4];
                acc[j4 * 4 + 0] += x * w.x;
                acc[j4 * 4 + 1] += x * w.y;
                acc[j4 * 4 + 2] += x * w.z;
                acc[j4 * 4 + 3] += x * w.w;
            }
        }
    }
    float4* yr = reinterpret_cast<float4*>(Y + (size_t)row * HD);
#pragma unroll
    for (int j4 = 0; j4 < HD / 4; j4++)
        yr[j4] = make_float4(acc[j4 * 4], acc[j4 * 4 + 1], acc[j4 * 4 + 2], acc[j4 * 4 + 3]);
}

// warp per edge: acc[dst] += feat[src]  (64 floats, float2 per lane, RED.ADD)
__global__ void scatter_add_k(const float* __restrict__ feat, float* __restrict__ acc,
                              const int* __restrict__ src, const int* __restrict__ dst, int nE) {
    int gw   = (blockIdx.x * blockDim.x + threadIdx.x) >> 5;
    int lane = threadIdx.x & 31;
    int nw   = (gridDim.x * blockDim.x) >> 5;
    for (int e = gw; e < nE; e += nw) {
        int s = __ldg(src + e);
        int d = __ldg(dst + e);
        float2 v = reinterpret_cast<const float2*>(feat + (size_t)s * HD)[lane];
        float* dp = acc + (size_t)d * HD + lane * 2;
        atomicAdd(dp, v.x);
        atomicAdd(dp + 1, v.y);
    }
}

__global__ void degree_k(const int* __restrict__ dst, int* __restrict__ deg, int nE) {
    int i = blockIdx.x * blockDim.x + threadIdx.x;
    if (i < nE) atomicAdd(deg + __ldg(dst + i), 1);
}

// out = (maybe relu)(agg/max(deg,1) + self + bias[col])
__global__ void combine_k(const float* __restrict__ agg, const float* __restrict__ self,
                          const float* __restrict__ bias, const int* __restrict__ deg,
                          float* __restrict__ out, int n, int do_relu) {
    int i = blockIdx.x * blockDim.x + threadIdx.x;
    if (i >= n * HD) return;
    int row = i >> 6, col = i & 63;
    float cnt = (float)max(__ldg(deg + row), 1);
    float v = agg[i] / cnt + self[i] + __ldg(bias + col);
    out[i] = (do_relu && v < 0.f) ? 0.f : v;
}

// warp per supervision edge: out = relu(u_c[r]+u_r[c]+b1) . w2 + b2
__global__ void decode_k(const float* __restrict__ u_c, const float* __restrict__ u_r,
                         const int* __restrict__ rows, const int* __restrict__ cols,
                         const float* __restrict__ b1, const float* __restrict__ w2,
                         const float* __restrict__ b2, float* __restrict__ out, int L) {
    int gw   = (blockIdx.x * blockDim.x + threadIdx.x) >> 5;
    int lane = threadIdx.x & 31;
    if (gw >= L) return;
    int r = __ldg(rows + gw);
    int c = __ldg(cols + gw);
    float2 a  = reinterpret_cast<const float2*>(u_c + (size_t)r * HD)[lane];
    float2 b  = reinterpret_cast<const float2*>(u_r + (size_t)c * HD)[lane];
    float2 bb = reinterpret_cast<const float2*>(b1)[lane];
    float2 w  = reinterpret_cast<const float2*>(w2)[lane];
    float h0 = fmaxf(a.x + b.x + bb.x, 0.f);
    float h1 = fmaxf(a.y + b.y + bb.y, 0.f);
    float s = h0 * w.x + h1 * w.y;
#pragma unroll
    for (int off = 16; off; off >>= 1) s += __shfl_xor_sync(0xffffffffu, s, off);
    if (lane == 0) out[gw] = s + __ldg(b2);
}

// ---------------- launch ----------------

extern "C" void kernel_launch(void* const* d_in, const int* in_sizes, int n_in,
                              void* d_out, int out_size) {
    const float* x_c   = (const float*)d_in[0];   // [NC,128]
    const float* x_r   = (const float*)d_in[1];   // [NR,64]
    const float* W1crl = (const float*)d_in[2];   // [128,64]
    const float* W1crr = (const float*)d_in[3];   // [64,64]
    const float* b1cr  = (const float*)d_in[4];
    const float* W1rcl = (const float*)d_in[5];   // [64,64]
    const float* W1rcr = (const float*)d_in[6];   // [128,64]
    const float* b1rc  = (const float*)d_in[7];
    const float* W2crl = (const float*)d_in[8];
    const float* W2crr = (const float*)d_in[9];
    const float* b2cr  = (const float*)d_in[10];
    const float* W2rcl = (const float*)d_in[11];
    const float* W2rcr = (const float*)d_in[12];
    const float* b2rc  = (const float*)d_in[13];
    const float* Wd1   = (const float*)d_in[14];  // [128,64]
    const float* bd1   = (const float*)d_in[15];
    const float* Wd2   = (const float*)d_in[16];  // [64]
    const float* bd2   = (const float*)d_in[17];  // [1]
    const int*   e_cr  = (const int*)d_in[18];    // [2,E]
    const int*   e_rc  = (const int*)d_in[19];    // [2,E]
    const int*   e_lab = (const int*)d_in[20];    // [2,L]
    const int E_ = in_sizes[18] / 2;
    const int L_ = in_sizes[20] / 2;

    float *t_c, *t_r, *s_r, *s_c, *a_r, *a_c, *h_r, *h_c;
    int *dg_r, *dg_c;
    cudaGetSymbolAddress((void**)&t_c, g_t_c);
    cudaGetSymbolAddress((void**)&t_r, g_t_r);
    cudaGetSymbolAddress((void**)&s_r, g_s_r);
    cudaGetSymbolAddress((void**)&s_c, g_s_c);
    cudaGetSymbolAddress((void**)&a_r, g_a_r);
    cudaGetSymbolAddress((void**)&a_c, g_a_c);
    cudaGetSymbolAddress((void**)&h_r, g_h_r);
    cudaGetSymbolAddress((void**)&h_c, g_h_c);
    cudaGetSymbolAddress((void**)&dg_r, g_dg_r);
    cudaGetSymbolAddress((void**)&dg_c, g_dg_c);

    const int NT = 256;
    const int nF   = NCN * HD;                  // feature buffer elems (same for NC/NR)
    const int gF4  = (nF / 4 + NT - 1) / NT;    // zero grid (float4)
    const int gD4  = (NCN / 4 + NT - 1) / NT;   // zero grid for deg
    const int gRow = (NCN + NT - 1) / NT;       // one thread per row
    const int gEw  = (E_ * 32 + NT - 1) / NT;   // warp per edge
    const int gE   = (E_ + NT - 1) / NT;
    const int gC   = (nF + NT - 1) / NT;
    const int gLw  = (L_ * 32 + NT - 1) / NT;

    const int* cr_s = e_cr;       const int* cr_d = e_cr + E_;
    const int* rc_s = e_rc;       const int* rc_d = e_rc + E_;
    const int* lb_r = e_lab;      const int* lb_c = e_lab + L_;

    // ---- degrees (constant across layers) ----
    zero_k<<<gD4, NT>>>((float4*)dg_r, NRN / 4);
    zero_k<<<gD4, NT>>>((float4*)dg_c, NCN / 4);
    degree_k<<<gE, NT>>>(cr_d, dg_r, E_);
    degree_k<<<gE, NT>>>(rc_d, dg_c, E_);

    // ---- layer 1 transforms ----
    gemm_nk<<<gRow, NT, 128 * HD * sizeof(float)>>>(x_c, W1crl, t_c, NCN, 128);
    gemm_nk<<<gRow, NT,  64 * HD * sizeof(float)>>>(x_r, W1crr, s_r, NRN, 64);
    gemm_nk<<<gRow, NT,  64 * HD * sizeof(float)>>>(x_r, W1rcl, t_r, NRN, 64);
    gemm_nk<<<gRow, NT, 128 * HD * sizeof(float)>>>(x_c, W1rcr, s_c, NCN, 128);

    // ---- layer 1 aggregate + combine (relu) ----
    zero_k<<<gF4, NT>>>((float4*)a_r, nF / 4);
    zero_k<<<gF4, NT>>>((float4*)a_c, nF / 4);
    scatter_add_k<<<gEw, NT>>>(t_c, a_r, cr_s, cr_d, E_);
    scatter_add_k<<<gEw, NT>>>(t_r, a_c, rc_s, rc_d, E_);
    combine_k<<<gC, NT>>>(a_r, s_r, b1cr, dg_r, h_r, NRN, 1);
    combine_k<<<gC, NT>>>(a_c, s_c, b1rc, dg_c, h_c, NCN, 1);

    // ---- layer 2 transforms ----
    gemm_nk<<<gRow, NT, 64 * HD * sizeof(float)>>>(h_c, W2crl, t_c, NCN, 64);
    gemm_nk<<<gRow, NT, 64 * HD * sizeof(float)>>>(h_r, W2crr, s_r, NRN, 64);
    gemm_nk<<<gRow, NT, 64 * HD * sizeof(float)>>>(h_r, W2rcl, t_r, NRN, 64);
    gemm_nk<<<gRow, NT, 64 * HD * sizeof(float)>>>(h_c, W2crr == W2rcr ? W2rcr : W2rcr, s_c, NCN, 64);

    // ---- layer 2 aggregate + combine (no relu) -> z in h buffers ----
    zero_k<<<gF4, NT>>>((float4*)a_r, nF / 4);
    zero_k<<<gF4, NT>>>((float4*)a_c, nF / 4);
    scatter_add_k<<<gEw, NT>>>(t_c, a_r, cr_s, cr_d, E_);
    scatter_add_k<<<gEw, NT>>>(t_r, a_c, rc_s, rc_d, E_);
    combine_k<<<gC, NT>>>(a_r, s_r, b2cr, dg_r, h_r, NRN, 0);  // z_r
    combine_k<<<gC, NT>>>(a_c, s_c, b2rc, dg_c, h_c, NCN, 0);  // z_c

    // ---- decoder precompute: u_c = z_c @ Wd1[0:64], u_r = z_r @ Wd1[64:128] ----
    gemm_nk<<<gRow, NT, 64 * HD * sizeof(float)>>>(h_c, Wd1,            t_c, NCN, 64);
    gemm_nk<<<gRow, NT, 64 * HD * sizeof(float)>>>(h_r, Wd1 + 64 * HD,  t_r, NRN, 64);

    // ---- decode ----
    decode_k<<<gLw, NT>>>(t_c, t_r, lb_r, lb_c, bd1, Wd2, bd2, (float*)d_out, L_);
}

// round 2
// speedup vs baseline: 1.8939x; 1.8939x over previous
#include <cuda_runtime.h>
#include <cuda_bf16.h>
#include <stdint.h>

#define NCN 100000
#define NRN 100000
#define HD  64
#define EMAX 2000000
#define SCAN_BS 256

// ---------------- scratch (device globals: allocation-free) ----------------
__device__ float g_t_c[(size_t)NCN * HD]; // transformed src (customer side) / u_c
__device__ float g_t_r[(size_t)NRN * HD]; // transformed src (recipe side)   / u_r
__device__ float g_s_r[(size_t)NRN * HD]; // self term for recipes
__device__ float g_s_c[(size_t)NCN * HD]; // self term for customers
__device__ float g_h_r[(size_t)NRN * HD]; // h_r then z_r
__device__ float g_h_c[(size_t)NCN * HD]; // h_c then z_c
__device__ int   g_dg_r[NRN];
__device__ int   g_dg_c[NCN];
__device__ int   g_off_r[NRN];
__device__ int   g_off_c[NCN];
__device__ int   g_cur_r[NRN];
__device__ int   g_cur_c[NCN];
__device__ int   g_csr_cr[EMAX];   // src ids grouped by dst, relation c->r
__device__ int   g_csr_rc[EMAX];   // src ids grouped by dst, relation r->c
__device__ int   g_bsum[1024];

// ---------------- kernels ----------------

__global__ void zero_i4(int4* __restrict__ p, int n4) {
    int i = blockIdx.x * blockDim.x + threadIdx.x;
    if (i < n4) p[i] = make_int4(0, 0, 0, 0);
}

__global__ void degree_k(const int* __restrict__ dst, int* __restrict__ deg, int nE) {
    int i = blockIdx.x * blockDim.x + threadIdx.x;
    if (i < nE) atomicAdd(deg + __ldg(dst + i), 1);
}

// --- 3-kernel exclusive scan over n<=100000 ints ---
__global__ void scan_block_k(const int* __restrict__ in, int* __restrict__ out,
                             int* __restrict__ bsum, int n) {
    __shared__ int sh[SCAN_BS];
    int i = blockIdx.x * SCAN_BS + threadIdx.x;
    int v = (i < n) ? in[i] : 0;
    sh[threadIdx.x] = v;
    __syncthreads();
    for (int off = 1; off < SCAN_BS; off <<= 1) {
        int t = (threadIdx.x >= off) ? sh[threadIdx.x - off] : 0;
        __syncthreads();
        sh[threadIdx.x] += t;
        __syncthreads();
    }
    if (i < n) out[i] = sh[threadIdx.x] - v;           // exclusive
    if (threadIdx.x == SCAN_BS - 1) bsum[blockIdx.x] = sh[threadIdx.x];
}

__global__ void scan_sums_k(int* __restrict__ bsum, int nb) {  // single block, nb<=1024
    __shared__ int sh[1024];
    int v = (threadIdx.x < nb) ? bsum[threadIdx.x] : 0;
    sh[threadIdx.x] = v;
    __syncthreads();
    for (int off = 1; off < 1024; off <<= 1) {
        int t = (threadIdx.x >= off) ? sh[threadIdx.x - off] : 0;
        __syncthreads();
        sh[threadIdx.x] += t;
        __syncthreads();
    }
    if (threadIdx.x < nb) bsum[threadIdx.x] = sh[threadIdx.x] - v;  // exclusive
}

__global__ void scan_add_copy_k(int* __restrict__ out, int* __restrict__ cur,
                                const int* __restrict__ bsum, int n) {
    int i = blockIdx.x * SCAN_BS + threadIdx.x;
    if (i < n) {
        int v = out[i] + bsum[blockIdx.x];
        out[i] = v;
        cur[i] = v;   // cursor copy for the fill pass
    }
}

__global__ void csr_fill_k(const int* __restrict__ src, const int* __restrict__ dst,
                           int* __restrict__ cur, int* __restrict__ csr, int nE) {
    int i = blockIdx.x * blockDim.x + threadIdx.x;
    if (i < nE) {
        int d = __ldg(dst + i);
        int p = atomicAdd(cur + d, 1);
        csr[p] = __ldg(src + i);
    }
}

// Y[n,64] = X[n,K] @ W[K,64].  W cached in shared; one thread per row.
__global__ void gemm_nk(const float* __restrict__ X, const float* __restrict__ W,
                        float* __restrict__ Y, int n, int K) {
    extern __shared__ float Ws[]; // K*64
    for (int i = threadIdx.x; i < K * HD; i += blockDim.x) Ws[i] = W[i];
    __syncthreads();
    int row = blockIdx.x * blockDim.x + threadIdx.x;
    if (row >= n) return;
    float acc[HD];
#pragma unroll
    for (int j = 0; j < HD; j++) acc[j] = 0.f;
    const float* xr = X + (size_t)row * K;
    for (int k = 0; k < K; k += 4) {
        float4 xv = *reinterpret_cast<const float4*>(xr + k);
        float xs[4] = {xv.x, xv.y, xv.z, xv.w};
#pragma unroll
        for (int kk = 0; kk < 4; kk++) {
            const float4* wrow = reinterpret_cast<const float4*>(Ws + (k + kk) * HD);
            float x = xs[kk];
#pragma unroll
            for (int j4 = 0; j4 < HD / 4; j4++) {
                float4 w = wrow[j4];
                acc[j4 * 4 + 0] += x * w.x;
                acc[j4 * 4 + 1] += x * w.y;
                acc[j4 * 4 + 2] += x * w.z;
                acc[j4 * 4 + 3] += x * w.w;
            }
        }
    }
    float4* yr = reinterpret_cast<float4*>(Y + (size_t)row * HD);
#pragma unroll
    for (int j4 = 0; j4 < HD / 4; j4++)
        yr[j4] = make_float4(acc[j4 * 4], acc[j4 * 4 + 1], acc[j4 * 4 + 2], acc[j4 * 4 + 3]);
}

// Fused gather-aggregate + mean + self + bias (+relu).
// One warp per dst node; float2 per lane (64 floats / row).
__global__ void aggregate_k(const float* __restrict__ feat, const float* __restrict__ self,
                            const float* __restrict__ bias, const int* __restrict__ offs,
                            const int* __restrict__ deg, const int* __restrict__ csr,
                            float* __restrict__ out, int n, int do_relu) {
    int w    = (blockIdx.x * blockDim.x + threadIdx.x) >> 5;
    int lane = threadIdx.x & 31;
    if (w >= n) return;
    int beg = __ldg(offs + w);
    int dg  = __ldg(deg + w);
    int end = beg + dg;
    float ax = 0.f, ay = 0.f, bx = 0.f, by = 0.f;
    int e = beg;
    // unroll-2: two independent gathers in flight
    for (; e + 1 < end; e += 2) {
        int s0 = __ldg(csr + e);
        int s1 = __ldg(csr + e + 1);
        float2 v0 = reinterpret_cast<const float2*>(feat + (size_t)s0 * HD)[lane];
        float2 v1 = reinterpret_cast<const float2*>(feat + (size_t)s1 * HD)[lane];
        ax += v0.x; ay += v0.y;
        bx += v1.x; by += v1.y;
    }
    if (e < end) {
        int s0 = __ldg(csr + e);
        float2 v0 = reinterpret_cast<const float2*>(feat + (size_t)s0 * HD)[lane];
        ax += v0.x; ay += v0.y;
    }
    ax += bx; ay += by;
    float inv = 1.f / (float)max(dg, 1);
    float2 sf = reinterpret_cast<const float2*>(self + (size_t)w * HD)[lane];
    float2 bb = reinterpret_cast<const float2*>(bias)[lane];
    float o0 = ax * inv + sf.x + bb.x;
    float o1 = ay * inv + sf.y + bb.y;
    if (do_relu) { o0 = fmaxf(o0, 0.f); o1 = fmaxf(o1, 0.f); }
    reinterpret_cast<float2*>(out + (size_t)w * HD)[lane] = make_float2(o0, o1);
}

// warp per supervision edge: out = relu(u_c[r]+u_r[c]+b1) . w2 + b2
__global__ void decode_k(const float* __restrict__ u_c, const float* __restrict__ u_r,
                         const int* __restrict__ rows, const int* __restrict__ cols,
                         const float* __restrict__ b1, const float* __restrict__ w2,
                         const float* __restrict__ b2, float* __restrict__ out, int L) {
    int gw   = (blockIdx.x * blockDim.x + threadIdx.x) >> 5;
    int lane = threadIdx.x & 31;
    if (gw >= L) return;
    int r = __ldg(rows + gw);
    int c = __ldg(cols + gw);
    float2 a  = reinterpret_cast<const float2*>(u_c + (size_t)r * HD)[lane];
    float2 b  = reinterpret_cast<const float2*>(u_r + (size_t)c * HD)[lane];
    float2 bb = reinterpret_cast<const float2*>(b1)[lane];
    float2 w  = reinterpret_cast<const float2*>(w2)[lane];
    float h0 = fmaxf(a.x + b.x + bb.x, 0.f);
    float h1 = fmaxf(a.y + b.y + bb.y, 0.f);
    float s = h0 * w.x + h1 * w.y;
#pragma unroll
    for (int off = 16; off; off >>= 1) s += __shfl_xor_sync(0xffffffffu, s, off);
    if (lane == 0) out[gw] = s + __ldg(b2);
}

// ---------------- launch ----------------

extern "C" void kernel_launch(void* const* d_in, const int* in_sizes, int n_in,
                              void* d_out, int out_size) {
    const float* x_c   = (const float*)d_in[0];   // [NC,128]
    const float* x_r   = (const float*)d_in[1];   // [NR,64]
    const float* W1crl = (const float*)d_in[2];
    const float* W1crr = (const float*)d_in[3];
    const float* b1cr  = (const float*)d_in[4];
    const float* W1rcl = (const float*)d_in[5];
    const float* W1rcr = (const float*)d_in[6];
    const float* b1rc  = (const float*)d_in[7];
    const float* W2crl = (const float*)d_in[8];
    const float* W2crr = (const float*)d_in[9];
    const float* b2cr  = (const float*)d_in[10];
    const float* W2rcl = (const float*)d_in[11];
    const float* W2rcr = (const float*)d_in[12];
    const float* b2rc  = (const float*)d_in[13];
    const float* Wd1   = (const float*)d_in[14];  // [128,64]
    const float* bd1   = (const float*)d_in[15];
    const float* Wd2   = (const float*)d_in[16];  // [64]
    const float* bd2   = (const float*)d_in[17];  // [1]
    const int*   e_cr  = (const int*)d_in[18];    // [2,E]
    const int*   e_rc  = (const int*)d_in[19];    // [2,E]
    const int*   e_lab = (const int*)d_in[20];    // [2,L]
    const int E_ = in_sizes[18] / 2;
    const int L_ = in_sizes[20] / 2;

    float *t_c, *t_r, *s_r, *s_c, *h_r, *h_c;
    int *dg_r, *dg_c, *off_r, *off_c, *cur_r, *cur_c, *csr_cr, *csr_rc, *bsum;
    cudaGetSymbolAddress((void**)&t_c, g_t_c);
    cudaGetSymbolAddress((void**)&t_r, g_t_r);
    cudaGetSymbolAddress((void**)&s_r, g_s_r);
    cudaGetSymbolAddress((void**)&s_c, g_s_c);
    cudaGetSymbolAddress((void**)&h_r, g_h_r);
    cudaGetSymbolAddress((void**)&h_c, g_h_c);
    cudaGetSymbolAddress((void**)&dg_r, g_dg_r);
    cudaGetSymbolAddress((void**)&dg_c, g_dg_c);
    cudaGetSymbolAddress((void**)&off_r, g_off_r);
    cudaGetSymbolAddress((void**)&off_c, g_off_c);
    cudaGetSymbolAddress((void**)&cur_r, g_cur_r);
    cudaGetSymbolAddress((void**)&cur_c, g_cur_c);
    cudaGetSymbolAddress((void**)&csr_cr, g_csr_cr);
    cudaGetSymbolAddress((void**)&csr_rc, g_csr_rc);
    cudaGetSymbolAddress((void**)&bsum, g_bsum);

    const int NT = 256;
    const int gD4  = (NCN / 4 + NT - 1) / NT;
    const int gRow = (NCN + NT - 1) / NT;       // one thread per row (gemm)
    const int gE   = (E_ + NT - 1) / NT;
    const int gNw  = (NCN * 32 + NT - 1) / NT;  // warp per dst node
    const int gLw  = (L_ * 32 + NT - 1) / NT;   // warp per label edge
    const int nScanB = (NCN + SCAN_BS - 1) / SCAN_BS;  // 391

    const int* cr_s = e_cr;   const int* cr_d = e_cr + E_;
    const int* rc_s = e_rc;   const int* rc_d = e_rc + E_;
    const int* lb_r = e_lab;  const int* lb_c = e_lab + L_;

    // ---- degrees ----
    zero_i4<<<gD4, NT>>>((int4*)dg_r, NRN / 4);
    zero_i4<<<gD4, NT>>>((int4*)dg_c, NCN / 4);
    degree_k<<<gE, NT>>>(cr_d, dg_r, E_);
    degree_k<<<gE, NT>>>(rc_d, dg_c, E_);

    // ---- CSR build: c->r (dst = recipes) ----
    scan_block_k<<<nScanB, SCAN_BS>>>(dg_r, off_r, bsum, NRN);
    scan_sums_k<<<1, 1024>>>(bsum, nScanB);
    scan_add_copy_k<<<nScanB, SCAN_BS>>>(off_r, cur_r, bsum, NRN);
    csr_fill_k<<<gE, NT>>>(cr_s, cr_d, cur_r, csr_cr, E_);
    // ---- CSR build: r->c (dst = customers) ----
    scan_block_k<<<nScanB, SCAN_BS>>>(dg_c, off_c, bsum, NCN);
    scan_sums_k<<<1, 1024>>>(bsum, nScanB);
    scan_add_copy_k<<<nScanB, SCAN_BS>>>(off_c, cur_c, bsum, NCN);
    csr_fill_k<<<gE, NT>>>(rc_s, rc_d, cur_c, csr_rc, E_);

    // ---- layer 1 transforms ----
    gemm_nk<<<gRow, NT, 128 * HD * sizeof(float)>>>(x_c, W1crl, t_c, NCN, 128);
    gemm_nk<<<gRow, NT,  64 * HD * sizeof(float)>>>(x_r, W1crr, s_r, NRN, 64);
    gemm_nk<<<gRow, NT,  64 * HD * sizeof(float)>>>(x_r, W1rcl, t_r, NRN, 64);
    gemm_nk<<<gRow, NT, 128 * HD * sizeof(float)>>>(x_c, W1rcr, s_c, NCN, 128);

    // ---- layer 1 gather-aggregate (fused mean+self+bias+relu) ----
    aggregate_k<<<gNw, NT>>>(t_c, s_r, b1cr, off_r, dg_r, csr_cr, h_r, NRN, 1);
    aggregate_k<<<gNw, NT>>>(t_r, s_c, b1rc, off_c, dg_c, csr_rc, h_c, NCN, 1);

    // ---- layer 2 transforms ----
    gemm_nk<<<gRow, NT, 64 * HD * sizeof(float)>>>(h_c, W2crl, t_c, NCN, 64);
    gemm_nk<<<gRow, NT, 64 * HD * sizeof(float)>>>(h_r, W2crr, s_r, NRN, 64);
    gemm_nk<<<gRow, NT, 64 * HD * sizeof(float)>>>(h_r, W2rcl, t_r, NRN, 64);
    gemm_nk<<<gRow, NT, 64 * HD * sizeof(float)>>>(h_c, W2rcr, s_c, NCN, 64);

    // ---- layer 2 gather-aggregate (no relu) -> z in h buffers ----
    aggregate_k<<<gNw, NT>>>(t_c, s_r, b2cr, off_r, dg_r, csr_cr, h_r, NRN, 0);  // z_r
    aggregate_k<<<gNw, NT>>>(t_r, s_c, b2rc, off_c, dg_c, csr_rc, h_c, NCN, 0);  // z_c

    // ---- decoder precompute: u_c = z_c @ Wd1[0:64], u_r = z_r @ Wd1[64:128] ----
    gemm_nk<<<gRow, NT, 64 * HD * sizeof(float)>>>(h_c, Wd1,           t_c, NCN, 64);
    gemm_nk<<<gRow, NT, 64 * HD * sizeof(float)>>>(h_r, Wd1 + 64 * HD, t_r, NRN, 64);

    // ---- decode ----
    decode_k<<<gLw, NT>>>(t_c, t_r, lb_r, lb_c, bd1, Wd2, bd2, (float*)d_out, L_);
}